// round 3
// baseline (speedup 1.0000x reference)
#include <cuda_runtime.h>
#include <math.h>

#define NN 50000
#define EE 800000
#define DD 128
#define OUTC 64

// ---------------- scratch (device globals; no allocation allowed) ----------
__device__ int   g_ei_is64;            // edge_index stored as int64?
__device__ int   g_m_is32;             // mask stored as int32?
__device__ int   g_row[EE];
__device__ int   g_col[EE];
__device__ unsigned char g_M[NN * DD];
__device__ int   g_deg[NN];
__device__ float g_dinv[NN];
__device__ int   g_off[NN + 1];
__device__ int   g_cur[NN];
__device__ int   g_src[EE];
__device__ float g_nrm[EE];
__device__ float g_xt[NN * DD];
__device__ float g_agg[NN * DD];
__device__ float g_h[NN * DD];

// ---------------- dtype detection (device-side, deterministic) -------------
// int64 indices (0 <= v < 2^31): every odd 32-bit word is 0.
// int32 mask: every 32-bit word is 0 or 1 (bool data would have bytes 1..3 set).
__global__ void k_detect(const int* __restrict__ ei,
                         const unsigned int* __restrict__ Mw) {
    __shared__ int s_or, s_gt;
    if (threadIdx.x == 0) { s_or = 0; s_gt = 0; }
    __syncthreads();
    int t = threadIdx.x;                 // 1024 threads
    if (ei[2 * t + 1] != 0) atomicOr(&s_or, 1);
    if (Mw[t] > 1u)         atomicOr(&s_gt, 1);
    __syncthreads();
    if (threadIdx.x == 0) {
        g_ei_is64 = (s_or == 0);
        g_m_is32  = (s_gt == 0);
    }
}

__global__ void k_norm_ei(const int* __restrict__ ei) {
    int e = blockIdx.x * blockDim.x + threadIdx.x;
    if (e >= EE) return;
    if (g_ei_is64) {
        g_row[e] = ei[2 * e];
        g_col[e] = ei[2 * (EE + e)];
    } else {
        g_row[e] = ei[e];
        g_col[e] = ei[EE + e];
    }
}

__global__ void k_norm_m(const void* __restrict__ M) {
    int i = blockIdx.x * blockDim.x + threadIdx.x;
    if (i >= NN * DD) return;
    g_M[i] = g_m_is32 ? (unsigned char)((const int*)M)[i]
                      : ((const unsigned char*)M)[i];
}

// ---------------- CSC construction ----------------------------------------
__global__ void k_zero() {
    int i = blockIdx.x * blockDim.x + threadIdx.x;
    if (i < NN) { g_deg[i] = 0; g_cur[i] = 0; }
}

__global__ void k_count() {
    int e = blockIdx.x * blockDim.x + threadIdx.x;
    if (e < EE) atomicAdd(&g_deg[g_col[e]], 1);
}

__global__ void k_dinv() {
    int i = blockIdx.x * blockDim.x + threadIdx.x;
    if (i < NN) {
        int d = g_deg[i];
        g_dinv[i] = (d > 0) ? rsqrtf((float)d) : 0.0f;
    }
}

// single-block scan of g_deg -> exclusive offsets g_off[0..NN]
__global__ void k_scan() {
    __shared__ int wsum[32];
    int tid = threadIdx.x;
    int lane = tid & 31, wid = tid >> 5;
    int carry = 0;
    for (int base = 0; base < NN; base += 1024) {
        int i = base + tid;
        int v = (i < NN) ? g_deg[i] : 0;
        int x = v;
#pragma unroll
        for (int o = 1; o < 32; o <<= 1) {
            int t = __shfl_up_sync(0xffffffffu, x, o);
            if (lane >= o) x += t;
        }
        if (lane == 31) wsum[wid] = x;
        __syncthreads();
        if (wid == 0) {
            int s = wsum[lane];
#pragma unroll
            for (int o = 1; o < 32; o <<= 1) {
                int t = __shfl_up_sync(0xffffffffu, s, o);
                if (lane >= o) s += t;
            }
            wsum[lane] = s;
        }
        __syncthreads();
        int woff = (wid > 0) ? wsum[wid - 1] : 0;
        int incl = carry + woff + x;
        if (i < NN) g_off[i + 1] = incl;
        carry += wsum[31];
        __syncthreads();
    }
    if (tid == 0) g_off[0] = 0;
}

__global__ void k_bucket() {
    int e = blockIdx.x * blockDim.x + threadIdx.x;
    if (e >= EE) return;
    int c = g_col[e];
    int r = g_row[e];
    int p = atomicAdd(&g_cur[c], 1);
    int idx = g_off[c] + p;
    g_src[idx] = r;
    g_nrm[idx] = g_dinv[r] * g_dinv[c];
}

// ---------------- x_tilde init for layer 1: x*M ----------------------------
__global__ void k_xt0(const float* __restrict__ x) {
    int i = blockIdx.x * blockDim.x + threadIdx.x;  // over (N*D)/4
    if (i >= NN * DD / 4) return;
    float4 xv = ((const float4*)x)[i];
    uchar4 mv = ((const uchar4*)g_M)[i];
    float4 r;
    r.x = mv.x ? xv.x : 0.0f;
    r.y = mv.y ? xv.y : 0.0f;
    r.z = mv.z ? xv.z : 0.0f;
    r.w = mv.w ? xv.w : 0.0f;
    ((float4*)g_xt)[i] = r;
}

// ---------------- SpMM: one warp per destination node ----------------------
__global__ void k_spmm() {
    int warp = (blockIdx.x * blockDim.x + threadIdx.x) >> 5;
    if (warp >= NN) return;
    int lane = threadIdx.x & 31;
    int s = g_off[warp];
    int t = g_off[warp + 1];
    const float4* xt4 = (const float4*)g_xt;
    float4 acc = make_float4(0.f, 0.f, 0.f, 0.f);
    for (int i = s; i < t; i++) {
        int src = g_src[i];
        float w = g_nrm[i];
        float4 v = xt4[src * 32 + lane];
        acc.x += w * v.x;
        acc.y += w * v.y;
        acc.z += w * v.z;
        acc.w += w * v.w;
    }
    ((float4*)g_agg)[warp * 32 + lane] = acc;
}

// ---------------- GEMM 128x128: h = relu(agg @ W^T + b + bias) -------------
// Static shared (<48KB), K staged in 4 chunks of 32.
// Block: 128 rows, 256 threads, 8x8 register microtile per thread.
__global__ void __launch_bounds__(256)
k_gemm_relu(const float* __restrict__ W,
            const float* __restrict__ b, const float* __restrict__ bias,
            const float* __restrict__ x, int write_xt) {
    __shared__ float sA[128 * 33];   // [r][kk], pad 33
    __shared__ float sW[32 * 129];   // [kk][j], pad 129
    __shared__ float sB[128];
    int tid = threadIdx.x;
    int row0 = blockIdx.x * 128;
    int tr = tid >> 4, tc = tid & 15;

    if (tid < 128) sB[tid] = b[tid] + bias[tid];

    float acc[8][8];
#pragma unroll
    for (int ii = 0; ii < 8; ii++)
#pragma unroll
        for (int jj = 0; jj < 8; jj++) acc[ii][jj] = 0.f;

    const float4* A4 = (const float4*)g_agg;
    const float4* W4 = (const float4*)W;

    for (int kc = 0; kc < 4; kc++) {
        int kq0 = kc * 8;  // float4 offset within a row
        for (int t = tid; t < 128 * 8; t += 256) {
            int r = t >> 3, q = t & 7;
            float4 v = (row0 + r < NN) ? A4[(size_t)(row0 + r) * 32 + kq0 + q]
                                       : make_float4(0.f, 0.f, 0.f, 0.f);
            float* dst = &sA[r * 33 + q * 4];
            dst[0] = v.x; dst[1] = v.y; dst[2] = v.z; dst[3] = v.w;
        }
        for (int t = tid; t < 128 * 8; t += 256) {
            int j = t >> 3, q = t & 7;
            float4 v = W4[j * 32 + kq0 + q];
            int kk = q * 4;
            sW[(kk + 0) * 129 + j] = v.x;
            sW[(kk + 1) * 129 + j] = v.y;
            sW[(kk + 2) * 129 + j] = v.z;
            sW[(kk + 3) * 129 + j] = v.w;
        }
        __syncthreads();
#pragma unroll
        for (int kk = 0; kk < 32; kk++) {
            float a[8], w[8];
#pragma unroll
            for (int ii = 0; ii < 8; ii++) a[ii] = sA[(tr + 16 * ii) * 33 + kk];
#pragma unroll
            for (int jj = 0; jj < 8; jj++) w[jj] = sW[kk * 129 + tc + 16 * jj];
#pragma unroll
            for (int ii = 0; ii < 8; ii++)
#pragma unroll
                for (int jj = 0; jj < 8; jj++) acc[ii][jj] += a[ii] * w[jj];
        }
        __syncthreads();
    }

#pragma unroll
    for (int ii = 0; ii < 8; ii++) {
        int r = row0 + tr + 16 * ii;
        if (r >= NN) continue;
#pragma unroll
        for (int jj = 0; jj < 8; jj++) {
            int j = tc + 16 * jj;
            float v = acc[ii][jj] + sB[j];
            v = fmaxf(v, 0.f);
            size_t idx = (size_t)r * DD + j;
            g_h[idx] = v;
            if (write_xt) g_xt[idx] = g_M[idx] ? x[idx] : v;
        }
    }
}

// ---------------- final GEMM: out = h @ Wf^T + bf  (N x 64) ----------------
__global__ void __launch_bounds__(256)
k_gemm_final(const float* __restrict__ Wf, const float* __restrict__ bf,
             float* __restrict__ out) {
    __shared__ float sA[128 * 33];   // [r][kk]
    __shared__ float sW[32 * 65];    // [kk][j], j<64
    __shared__ float sB[64];
    int tid = threadIdx.x;
    int row0 = blockIdx.x * 128;
    int tr = tid >> 4, tc = tid & 15;

    if (tid < 64) sB[tid] = bf[tid];

    float acc[8][4];
#pragma unroll
    for (int ii = 0; ii < 8; ii++)
#pragma unroll
        for (int jj = 0; jj < 4; jj++) acc[ii][jj] = 0.f;

    const float4* A4 = (const float4*)g_h;
    const float4* W4 = (const float4*)Wf;

    for (int kc = 0; kc < 4; kc++) {
        int kq0 = kc * 8;
        for (int t = tid; t < 128 * 8; t += 256) {
            int r = t >> 3, q = t & 7;
            float4 v = (row0 + r < NN) ? A4[(size_t)(row0 + r) * 32 + kq0 + q]
                                       : make_float4(0.f, 0.f, 0.f, 0.f);
            float* dst = &sA[r * 33 + q * 4];
            dst[0] = v.x; dst[1] = v.y; dst[2] = v.z; dst[3] = v.w;
        }
        for (int t = tid; t < 64 * 8; t += 256) {
            int j = t >> 3, q = t & 7;
            float4 v = W4[j * 32 + kq0 + q];
            int kk = q * 4;
            sW[(kk + 0) * 65 + j] = v.x;
            sW[(kk + 1) * 65 + j] = v.y;
            sW[(kk + 2) * 65 + j] = v.z;
            sW[(kk + 3) * 65 + j] = v.w;
        }
        __syncthreads();
#pragma unroll
        for (int kk = 0; kk < 32; kk++) {
            float a[8], w[4];
#pragma unroll
            for (int ii = 0; ii < 8; ii++) a[ii] = sA[(tr + 16 * ii) * 33 + kk];
#pragma unroll
            for (int jj = 0; jj < 4; jj++) w[jj] = sW[kk * 65 + tc + 16 * jj];
#pragma unroll
            for (int ii = 0; ii < 8; ii++)
#pragma unroll
                for (int jj = 0; jj < 4; jj++) acc[ii][jj] += a[ii] * w[jj];
        }
        __syncthreads();
    }

#pragma unroll
    for (int ii = 0; ii < 8; ii++) {
        int r = row0 + tr + 16 * ii;
        if (r >= NN) continue;
#pragma unroll
        for (int jj = 0; jj < 4; jj++) {
            int j = tc + 16 * jj;
            out[(size_t)r * OUTC + j] = acc[ii][jj] + sB[j];
        }
    }
}

// ---------------- launch ----------------------------------------------------
extern "C" void kernel_launch(void* const* d_in, const int* in_sizes, int n_in,
                              void* d_out, int out_size) {
    const int* ei = (const int*)d_in[0];   // [2, E]; int32 or int64 (detected)
    // d_in[1] = edge_weight (unused by the model)
    const float* x = (const float*)d_in[2];
    const void*  M = d_in[3];              // bool or int32 (detected)
    const float* W1 = (const float*)d_in[4];
    const float* b1 = (const float*)d_in[5];
    const float* c1 = (const float*)d_in[6];
    const float* W2 = (const float*)d_in[7];
    const float* b2 = (const float*)d_in[8];
    const float* c2 = (const float*)d_in[9];
    const float* W3 = (const float*)d_in[10];
    const float* b3 = (const float*)d_in[11];
    const float* c3 = (const float*)d_in[12];
    const float* Wf = (const float*)d_in[13];
    const float* bf = (const float*)d_in[14];
    float* out = (float*)d_out;

    const int TB = 256;
    int nb_n = (NN + TB - 1) / TB;
    int nb_e = (EE + TB - 1) / TB;
    int nb_m = (NN * DD + TB - 1) / TB;
    int nb_xt = (NN * DD / 4 + TB - 1) / TB;
    int nb_spmm = (NN * 32 + TB - 1) / TB;   // 1 warp per node
    int nb_gemm = (NN + 127) / 128;

    // dtype detection + normalization
    k_detect<<<1, 1024>>>(ei, (const unsigned int*)M);
    k_norm_ei<<<nb_e, TB>>>(ei);
    k_norm_m<<<nb_m, TB>>>(M);

    // CSC build
    k_zero<<<nb_n, TB>>>();
    k_count<<<nb_e, TB>>>();
    k_dinv<<<nb_n, TB>>>();
    k_scan<<<1, 1024>>>();
    k_bucket<<<nb_e, TB>>>();

    // layer 1
    k_xt0<<<nb_xt, TB>>>(x);
    k_spmm<<<nb_spmm, TB>>>();
    k_gemm_relu<<<nb_gemm, TB>>>(W1, b1, c1, x, 1);
    // layer 2
    k_spmm<<<nb_spmm, TB>>>();
    k_gemm_relu<<<nb_gemm, TB>>>(W2, b2, c2, x, 1);
    // layer 3
    k_spmm<<<nb_spmm, TB>>>();
    k_gemm_relu<<<nb_gemm, TB>>>(W3, b3, c3, x, 0);
    // final fc
    k_gemm_final<<<nb_gemm, TB>>>(Wf, bf, out);
}

// round 5
// speedup vs baseline: 1.3055x; 1.3055x over previous
#include <cuda_runtime.h>
#include <math.h>
#include <stdint.h>

#define NN 50000
#define EE 800000
#define DD 128
#define OUTC 64

typedef unsigned long long u64;

// ---------------- scratch (device globals; no allocation allowed) ----------
__device__ int   g_ei_is64;
__device__ int   g_m_is32;
__device__ unsigned char g_M[NN * DD];
__device__ int   g_deg[NN];
__device__ float g_dinv[NN];
__device__ int   g_off[NN + 1];
__device__ int   g_cur[NN];
__device__ int   g_src[EE];
__device__ float g_nrm[EE];
__device__ float g_xt[NN * DD];
__device__ float g_agg[NN * DD];
__device__ float g_h[NN * DD];

// ---------------- f32x2 packed math ----------------------------------------
__device__ __forceinline__ u64 pack2(float s) {
    u64 d;
    asm("mov.b64 %0, {%1, %1};" : "=l"(d) : "f"(s));
    return d;
}
__device__ __forceinline__ void fma2(u64& acc, u64 a, u64 b) {
    asm("fma.rn.f32x2 %0, %1, %2, %0;" : "+l"(acc) : "l"(a), "l"(b));
}
__device__ __forceinline__ float2 unpack2(u64 v) {
    float lo, hi;
    asm("mov.b64 {%0, %1}, %2;" : "=f"(lo), "=f"(hi) : "l"(v));
    return make_float2(lo, hi);
}

// ---------------- init: zero deg/cur + dtype detection (block 0) ------------
__global__ void k_init(const int* __restrict__ ei, const unsigned int* __restrict__ Mw) {
    int i = blockIdx.x * blockDim.x + threadIdx.x;
    if (i < NN) { g_deg[i] = 0; g_cur[i] = 0; }
    if (blockIdx.x == 0) {
        __shared__ int s_or, s_gt;
        if (threadIdx.x == 0) { s_or = 0; s_gt = 0; }
        __syncthreads();
        int t = threadIdx.x;              // 256 probes each
        if (ei[2 * t + 1] != 0) atomicOr(&s_or, 1);
        if (Mw[t] > 1u)         atomicOr(&s_gt, 1);
        __syncthreads();
        if (threadIdx.x == 0) { g_ei_is64 = (s_or == 0); g_m_is32 = (s_gt == 0); }
    }
}

// ---------------- CSC build -------------------------------------------------
__global__ void k_count(const int* __restrict__ ei) {
    int e = blockIdx.x * blockDim.x + threadIdx.x;
    if (e >= EE) return;
    int c = g_ei_is64 ? ei[2 * (EE + e)] : ei[EE + e];
    atomicAdd(&g_deg[c], 1);
}

// single-block scan of g_deg -> g_off, plus dinv
__global__ void k_scan_dinv() {
    __shared__ int wsum[32];
    int tid = threadIdx.x, lane = tid & 31, wid = tid >> 5;
    int carry = 0;
    for (int base = 0; base < NN; base += 1024) {
        int i = base + tid;
        int v = (i < NN) ? g_deg[i] : 0;
        if (i < NN) g_dinv[i] = (v > 0) ? rsqrtf((float)v) : 0.0f;
        int x = v;
#pragma unroll
        for (int o = 1; o < 32; o <<= 1) {
            int t = __shfl_up_sync(0xffffffffu, x, o);
            if (lane >= o) x += t;
        }
        if (lane == 31) wsum[wid] = x;
        __syncthreads();
        if (wid == 0) {
            int s = wsum[lane];
#pragma unroll
            for (int o = 1; o < 32; o <<= 1) {
                int t = __shfl_up_sync(0xffffffffu, s, o);
                if (lane >= o) s += t;
            }
            wsum[lane] = s;
        }
        __syncthreads();
        int woff = (wid > 0) ? wsum[wid - 1] : 0;
        if (i < NN) g_off[i + 1] = carry + woff + x;
        carry += wsum[31];
        __syncthreads();
    }
    if (tid == 0) g_off[0] = 0;
}

__global__ void k_bucket(const int* __restrict__ ei) {
    int e = blockIdx.x * blockDim.x + threadIdx.x;
    if (e >= EE) return;
    int r, c;
    if (g_ei_is64) { r = ei[2 * e]; c = ei[2 * (EE + e)]; }
    else           { r = ei[e];     c = ei[EE + e]; }
    int p = atomicAdd(&g_cur[c], 1);
    int idx = g_off[c] + p;
    g_src[idx] = r;
    g_nrm[idx] = g_dinv[r] * g_dinv[c];
}

// ---------------- x_tilde init + mask normalize -----------------------------
__global__ void k_xt0m(const float* __restrict__ x, const void* __restrict__ M) {
    int i = blockIdx.x * blockDim.x + threadIdx.x;   // over (N*D)/4
    if (i >= NN * DD / 4) return;
    uchar4 mv;
    if (g_m_is32) {
        int4 w = ((const int4*)M)[i];
        mv = make_uchar4((unsigned char)w.x, (unsigned char)w.y,
                         (unsigned char)w.z, (unsigned char)w.w);
    } else {
        mv = ((const uchar4*)M)[i];
    }
    ((uchar4*)g_M)[i] = mv;
    float4 xv = ((const float4*)x)[i];
    float4 r;
    r.x = mv.x ? xv.x : 0.0f;
    r.y = mv.y ? xv.y : 0.0f;
    r.z = mv.z ? xv.z : 0.0f;
    r.w = mv.w ? xv.w : 0.0f;
    ((float4*)g_xt)[i] = r;
}

// ---------------- SpMM: one warp per destination node, unroll 4 -------------
__global__ void k_spmm() {
    int warp = (blockIdx.x * blockDim.x + threadIdx.x) >> 5;
    if (warp >= NN) return;
    int lane = threadIdx.x & 31;
    int s = g_off[warp], t = g_off[warp + 1];
    const float4* xt4 = (const float4*)g_xt;
    float4 acc = make_float4(0.f, 0.f, 0.f, 0.f);
    int i = s;
    for (; i + 4 <= t; i += 4) {
        int   s0 = g_src[i],   s1 = g_src[i+1], s2 = g_src[i+2], s3 = g_src[i+3];
        float w0 = g_nrm[i],   w1 = g_nrm[i+1], w2 = g_nrm[i+2], w3 = g_nrm[i+3];
        float4 v0 = xt4[s0 * 32 + lane];
        float4 v1 = xt4[s1 * 32 + lane];
        float4 v2 = xt4[s2 * 32 + lane];
        float4 v3 = xt4[s3 * 32 + lane];
        acc.x += w0*v0.x; acc.y += w0*v0.y; acc.z += w0*v0.z; acc.w += w0*v0.w;
        acc.x += w1*v1.x; acc.y += w1*v1.y; acc.z += w1*v1.z; acc.w += w1*v1.w;
        acc.x += w2*v2.x; acc.y += w2*v2.y; acc.z += w2*v2.z; acc.w += w2*v2.w;
        acc.x += w3*v3.x; acc.y += w3*v3.y; acc.z += w3*v3.z; acc.w += w3*v3.w;
    }
    for (; i < t; i++) {
        int src = g_src[i];
        float w = g_nrm[i];
        float4 v = xt4[src * 32 + lane];
        acc.x += w*v.x; acc.y += w*v.y; acc.z += w*v.z; acc.w += w*v.w;
    }
    ((float4*)g_agg)[warp * 32 + lane] = acc;
}

// ---------------- GEMM with packed f32x2 FMA ---------------------------------
// D[128 x NOUT] = A[128 x 128] @ W[NOUT x 128]^T, A = g_agg (g_h for FINAL).
// 256 threads, 8 rows x (NOUT/32 col-pairs*... 8 or 4 cols) microtile, K in 4
// chunks of 32. Columns handled as f32x2 pairs: j0 = 2*tc + 32*jj.
template <int NOUT, bool FINAL>
__global__ void __launch_bounds__(256)
k_gemm(const float* __restrict__ W, const float* __restrict__ b,
       const float* __restrict__ bias, const float* __restrict__ x,
       float* __restrict__ out, int write_xt) {
    constexpr int NPAIR = NOUT / 32;     // 4 (hidden) or 2 (final)
    __shared__ float sA[128 * 33];       // [r][kk]
    __shared__ float sW[32 * 130];       // [kk][j], stride 130 keeps 8B align
    __shared__ float sB[128];
    int tid = threadIdx.x;
    int row0 = blockIdx.x * 128;
    int tr = tid >> 4, tc = tid & 15;

    if (tid < NOUT) sB[tid] = FINAL ? b[tid] : (b[tid] + bias[tid]);

    u64 acc[8][NPAIR];
#pragma unroll
    for (int ii = 0; ii < 8; ii++)
#pragma unroll
        for (int jj = 0; jj < NPAIR; jj++) acc[ii][jj] = 0ull;

    const float4* A4 = (const float4*)(FINAL ? g_h : g_agg);
    const float4* W4 = (const float4*)W;

    for (int kc = 0; kc < 4; kc++) {
        int kq0 = kc * 8;
        for (int t = tid; t < 128 * 8; t += 256) {
            int r = t >> 3, q = t & 7;
            float4 v = (row0 + r < NN) ? A4[(size_t)(row0 + r) * 32 + kq0 + q]
                                       : make_float4(0.f, 0.f, 0.f, 0.f);
            float* dst = &sA[r * 33 + q * 4];
            dst[0] = v.x; dst[1] = v.y; dst[2] = v.z; dst[3] = v.w;
        }
        for (int t = tid; t < NOUT * 8; t += 256) {
            int j = t >> 3, q = t & 7;
            float4 v = W4[(size_t)j * 32 + kq0 + q];
            int kk = q * 4;
            sW[(kk + 0) * 130 + j] = v.x;
            sW[(kk + 1) * 130 + j] = v.y;
            sW[(kk + 2) * 130 + j] = v.z;
            sW[(kk + 3) * 130 + j] = v.w;
        }
        __syncthreads();
#pragma unroll
        for (int kk = 0; kk < 32; kk++) {
            u64 a2[8], w2[NPAIR];
#pragma unroll
            for (int ii = 0; ii < 8; ii++)
                a2[ii] = pack2(sA[(tr + 16 * ii) * 33 + kk]);
#pragma unroll
            for (int jj = 0; jj < NPAIR; jj++)
                w2[jj] = *(const u64*)&sW[kk * 130 + 2 * tc + 32 * jj];
#pragma unroll
            for (int ii = 0; ii < 8; ii++)
#pragma unroll
                for (int jj = 0; jj < NPAIR; jj++)
                    fma2(acc[ii][jj], a2[ii], w2[jj]);
        }
        __syncthreads();
    }

#pragma unroll
    for (int ii = 0; ii < 8; ii++) {
        int r = row0 + tr + 16 * ii;
        if (r >= NN) continue;
#pragma unroll
        for (int jj = 0; jj < NPAIR; jj++) {
            int j0 = 2 * tc + 32 * jj;
            float2 v = unpack2(acc[ii][jj]);
            if (FINAL) {
                v.x += sB[j0];
                v.y += sB[j0 + 1];
                *(float2*)&out[(size_t)r * OUTC + j0] = v;
            } else {
                v.x = fmaxf(v.x + sB[j0], 0.f);
                v.y = fmaxf(v.y + sB[j0 + 1], 0.f);
                size_t idx = (size_t)r * DD + j0;
                *(float2*)&g_h[idx] = v;
                if (write_xt) {
                    unsigned char m0 = g_M[idx], m1 = g_M[idx + 1];
                    float2 xv = *(const float2*)&x[idx];
                    float2 tv;
                    tv.x = m0 ? xv.x : v.x;
                    tv.y = m1 ? xv.y : v.y;
                    *(float2*)&g_xt[idx] = tv;
                }
            }
        }
    }
}

// ---------------- launch ----------------------------------------------------
extern "C" void kernel_launch(void* const* d_in, const int* in_sizes, int n_in,
                              void* d_out, int out_size) {
    const int* ei = (const int*)d_in[0];   // [2,E], int32 or int64 (detected)
    const float* x = (const float*)d_in[2];
    const void*  M = d_in[3];              // bool or int32 (detected)
    const float* W1 = (const float*)d_in[4];
    const float* b1 = (const float*)d_in[5];
    const float* c1 = (const float*)d_in[6];
    const float* W2 = (const float*)d_in[7];
    const float* b2 = (const float*)d_in[8];
    const float* c2 = (const float*)d_in[9];
    const float* W3 = (const float*)d_in[10];
    const float* b3 = (const float*)d_in[11];
    const float* c3 = (const float*)d_in[12];
    const float* Wf = (const float*)d_in[13];
    const float* bf = (const float*)d_in[14];
    float* out = (float*)d_out;

    const int TB = 256;
    int nb_n = (NN + TB - 1) / TB;
    int nb_e = (EE + TB - 1) / TB;
    int nb_xt = (NN * DD / 4 + TB - 1) / TB;
    int nb_spmm = (NN * 32 + TB - 1) / TB;
    int nb_gemm = (NN + 127) / 128;

    k_init<<<nb_n, TB>>>(ei, (const unsigned int*)M);
    k_count<<<nb_e, TB>>>(ei);
    k_scan_dinv<<<1, 1024>>>();
    k_bucket<<<nb_e, TB>>>(ei);
    k_xt0m<<<nb_xt, TB>>>(x, M);

    k_spmm<<<nb_spmm, TB>>>();
    k_gemm<128, false><<<nb_gemm, TB>>>(W1, b1, c1, x, nullptr, 1);
    k_spmm<<<nb_spmm, TB>>>();
    k_gemm<128, false><<<nb_gemm, TB>>>(W2, b2, c2, x, nullptr, 1);
    k_spmm<<<nb_spmm, TB>>>();
    k_gemm<128, false><<<nb_gemm, TB>>>(W3, b3, c3, x, nullptr, 0);
    k_gemm<64, true><<<nb_gemm, TB>>>(Wf, bf, nullptr, nullptr, out, 0);
}